// round 1
// baseline (speedup 1.0000x reference)
#include <cuda_runtime.h>
#include <math.h>

#define N_NODES 50000
#define N_EDGES 800000
#define D 64

// ---------------- scratch (device globals: no allocation allowed) ----------------
__device__ float        g_sent[N_NODES * D];
__device__ float        g_recv[N_NODES * D];
__device__ float        g_msg [N_NODES * D];
__device__ float        g_logit[N_EDGES];
__device__ unsigned int g_maxenc[N_NODES];
__device__ int          g_count[N_NODES];
__device__ int          g_rowoff[N_NODES + 1];
__device__ int          g_cursor[N_NODES];
__device__ int          g_csr[N_EDGES];

// float <-> ordered-uint encoding for atomicMax on signed floats
__device__ __forceinline__ unsigned int enc_f(float f) {
    unsigned int u = __float_as_uint(f);
    return (u & 0x80000000u) ? ~u : (u | 0x80000000u);
}
__device__ __forceinline__ float dec_f(unsigned int u) {
    return (u & 0x80000000u) ? __uint_as_float(u & 0x7fffffffu)
                             : __uint_as_float(~u);
}

// ---------------- K0: init ----------------
__global__ void k_init() {
    int i = blockIdx.x * blockDim.x + threadIdx.x;
    if (i < N_NODES) { g_maxenc[i] = 0u; g_count[i] = 0; }
}

// ---------------- K1: node projections (sent/recv/msg -> scratch, self -> d_out) ----------------
// Tile: 128 nodes x 64 cols, 256 threads, each thread 4 rows x 8 cols, 4 weight passes.
__global__ void k_node(const float* __restrict__ nodes,
                       const float* __restrict__ Ws, const float* __restrict__ bs,
                       const float* __restrict__ Wr, const float* __restrict__ br,
                       const float* __restrict__ Wm, const float* __restrict__ bm,
                       const float* __restrict__ Wf, const float* __restrict__ bf,
                       float* __restrict__ out_self)
{
    extern __shared__ float sm[];
    float (*sA)[65] = (float(*)[65])sm;       // 128 x 65 (pad -> conflict-free A reads)
    float* sW = sm + 128 * 65;                // 64 x 64
    float* sb = sW + 64 * 64;                 // 64

    int tx = threadIdx.x;
    int n0 = blockIdx.x * 128;

    const float4* nd4 = (const float4*)nodes;
    for (int i = tx; i < 128 * 16; i += 256) {
        int row = i >> 4, c = (i & 15) * 4;
        float4 v = make_float4(0.f, 0.f, 0.f, 0.f);
        int gr = n0 + row;
        if (gr < N_NODES) v = nd4[(size_t)gr * 16 + (i & 15)];
        sA[row][c] = v.x; sA[row][c + 1] = v.y; sA[row][c + 2] = v.z; sA[row][c + 3] = v.w;
    }

    int cb = tx & 7, eb = tx >> 3;
    int c0 = cb * 8;

    const float* Wlist[4] = {Ws, Wr, Wm, Wf};
    const float* blist[4] = {bs, br, bm, bf};
    float*       olist[4] = {g_sent, g_recv, g_msg, out_self};

    #pragma unroll
    for (int m = 0; m < 4; m++) {
        __syncthreads();
        const float* W = Wlist[m];
        for (int i = tx; i < 4096; i += 256) sW[i] = W[i];
        if (tx < 64) sb[tx] = blist[m][tx];
        __syncthreads();

        float acc[4][8];
        #pragma unroll
        for (int i = 0; i < 4; i++)
            #pragma unroll
            for (int j = 0; j < 8; j++) acc[i][j] = 0.f;

        #pragma unroll 4
        for (int k = 0; k < 64; k++) {
            float4 w0 = *(const float4*)&sW[k * 64 + c0];
            float4 w1 = *(const float4*)&sW[k * 64 + c0 + 4];
            #pragma unroll
            for (int i = 0; i < 4; i++) {
                float a = sA[eb * 4 + i][k];
                acc[i][0] += a * w0.x; acc[i][1] += a * w0.y;
                acc[i][2] += a * w0.z; acc[i][3] += a * w0.w;
                acc[i][4] += a * w1.x; acc[i][5] += a * w1.y;
                acc[i][6] += a * w1.z; acc[i][7] += a * w1.w;
            }
        }

        float4 b0 = *(const float4*)&sb[c0];
        float4 b1 = *(const float4*)&sb[c0 + 4];
        float* out = olist[m];
        #pragma unroll
        for (int i = 0; i < 4; i++) {
            int gr = n0 + eb * 4 + i;
            if (gr < N_NODES) {
                float4 o0 = make_float4(acc[i][0] + b0.x, acc[i][1] + b0.y,
                                        acc[i][2] + b0.z, acc[i][3] + b0.w);
                float4 o1 = make_float4(acc[i][4] + b1.x, acc[i][5] + b1.y,
                                        acc[i][6] + b1.z, acc[i][7] + b1.w);
                *(float4*)&out[(size_t)gr * 64 + c0]     = o0;
                *(float4*)&out[(size_t)gr * 64 + c0 + 4] = o1;
            }
        }
    }
}

// ---------------- K2: edge GEMM + fused epilogue ----------------
// edge_feat = edges@W_edge + b_edge + sent[s] + recv[r]; logit = lrelu(ef . W_attn + b_attn)
// + atomicMax segment max + receiver degree count.
__global__ void k_edge(const float* __restrict__ edges,
                       const int* __restrict__ senders, const int* __restrict__ receivers,
                       const float* __restrict__ W_edge, const float* __restrict__ b_edge,
                       const float* __restrict__ W_attn, const float* __restrict__ b_attn,
                       float* __restrict__ edge_feat)
{
    extern __shared__ float sm[];
    float (*sA)[65] = (float(*)[65])sm;       // 128 x 65
    float* sW  = sm + 128 * 65;               // 64 x 64
    float* sb  = sW + 4096;                   // 64
    float* swa = sb + 64;                     // 64

    int tx = threadIdx.x;
    int e0 = blockIdx.x * 128;                // N_EDGES % 128 == 0

    const float4* eg4 = (const float4*)(edges + (size_t)e0 * 64);
    for (int i = tx; i < 128 * 16; i += 256) {
        float4 v = eg4[i];
        int row = i >> 4, c = (i & 15) * 4;
        sA[row][c] = v.x; sA[row][c + 1] = v.y; sA[row][c + 2] = v.z; sA[row][c + 3] = v.w;
    }
    for (int i = tx; i < 4096; i += 256) sW[i] = W_edge[i];
    if (tx < 64) { sb[tx] = b_edge[tx]; swa[tx] = W_attn[tx]; }
    __syncthreads();

    int cb = tx & 7, eb = tx >> 3;
    int c0 = cb * 8;

    float acc[4][8];
    #pragma unroll
    for (int i = 0; i < 4; i++)
        #pragma unroll
        for (int j = 0; j < 8; j++) acc[i][j] = 0.f;

    #pragma unroll 4
    for (int k = 0; k < 64; k++) {
        float4 w0 = *(const float4*)&sW[k * 64 + c0];
        float4 w1 = *(const float4*)&sW[k * 64 + c0 + 4];
        #pragma unroll
        for (int i = 0; i < 4; i++) {
            float a = sA[eb * 4 + i][k];
            acc[i][0] += a * w0.x; acc[i][1] += a * w0.y;
            acc[i][2] += a * w0.z; acc[i][3] += a * w0.w;
            acc[i][4] += a * w1.x; acc[i][5] += a * w1.y;
            acc[i][6] += a * w1.z; acc[i][7] += a * w1.w;
        }
    }

    float4 b0 = *(const float4*)&sb[c0];
    float4 b1 = *(const float4*)&sb[c0 + 4];
    float wa[8];
    #pragma unroll
    for (int j = 0; j < 8; j++) wa[j] = swa[c0 + j];
    float battn = b_attn[0];

    #pragma unroll
    for (int i = 0; i < 4; i++) {
        int e = e0 + eb * 4 + i;
        int s = senders[e], r = receivers[e];
        const float4* ps = (const float4*)(g_sent + (size_t)s * 64 + c0);
        const float4* pr = (const float4*)(g_recv + (size_t)r * 64 + c0);
        float4 sv0 = ps[0], sv1 = ps[1];
        float4 rv0 = pr[0], rv1 = pr[1];

        float ef[8];
        ef[0] = acc[i][0] + b0.x + sv0.x + rv0.x;
        ef[1] = acc[i][1] + b0.y + sv0.y + rv0.y;
        ef[2] = acc[i][2] + b0.z + sv0.z + rv0.z;
        ef[3] = acc[i][3] + b0.w + sv0.w + rv0.w;
        ef[4] = acc[i][4] + b1.x + sv1.x + rv1.x;
        ef[5] = acc[i][5] + b1.y + sv1.y + rv1.y;
        ef[6] = acc[i][6] + b1.z + sv1.z + rv1.z;
        ef[7] = acc[i][7] + b1.w + sv1.w + rv1.w;

        *(float4*)&edge_feat[(size_t)e * 64 + c0]     = make_float4(ef[0], ef[1], ef[2], ef[3]);
        *(float4*)&edge_feat[(size_t)e * 64 + c0 + 4] = make_float4(ef[4], ef[5], ef[6], ef[7]);

        float p = ef[0]*wa[0] + ef[1]*wa[1] + ef[2]*wa[2] + ef[3]*wa[3]
                + ef[4]*wa[4] + ef[5]*wa[5] + ef[6]*wa[6] + ef[7]*wa[7];
        p += __shfl_xor_sync(0xffffffffu, p, 1);
        p += __shfl_xor_sync(0xffffffffu, p, 2);
        p += __shfl_xor_sync(0xffffffffu, p, 4);
        if (cb == 0) {
            float l = p + battn;
            l = (l > 0.f) ? l : 0.01f * l;     // jax.nn.leaky_relu default slope 0.01
            g_logit[e] = l;
            atomicMax(&g_maxenc[r], enc_f(l));
            atomicAdd(&g_count[r], 1);
        }
    }
}

// ---------------- K3: single-block exclusive scan over degrees ----------------
__global__ void k_scan() {
    __shared__ int part[1024];
    int t = threadIdx.x;
    const int CH = (N_NODES + 1023) / 1024;   // 49
    int base = t * CH;
    int s = 0;
    for (int i = 0; i < CH; i++) {
        int idx = base + i;
        if (idx < N_NODES) s += g_count[idx];
    }
    part[t] = s;
    __syncthreads();
    for (int off = 1; off < 1024; off <<= 1) {
        int v = 0;
        if (t >= off) v = part[t - off];
        __syncthreads();
        if (t >= off) part[t] += v;
        __syncthreads();
    }
    int run = (t == 0) ? 0 : part[t - 1];
    for (int i = 0; i < CH; i++) {
        int idx = base + i;
        if (idx < N_NODES) {
            g_rowoff[idx] = run;
            g_cursor[idx] = run;
            run += g_count[idx];
        }
    }
    if (t == 1023) g_rowoff[N_NODES] = part[1023];
}

// ---------------- K4: CSR fill ----------------
__global__ void k_fill(const int* __restrict__ receivers) {
    int e = blockIdx.x * blockDim.x + threadIdx.x;
    if (e < N_EDGES) {
        int r = receivers[e];
        int slot = atomicAdd(&g_cursor[r], 1);
        g_csr[slot] = e;
    }
}

// ---------------- K5: warp-per-node softmax-weighted aggregation ----------------
__global__ void k_aggregate(const int* __restrict__ senders,
                            float* __restrict__ out_nodes)
{
    int gid = blockIdx.x * blockDim.x + threadIdx.x;
    int n = gid >> 5;
    if (n >= N_NODES) return;
    int lane = gid & 31;
    int off = g_rowoff[n];
    int deg = g_rowoff[n + 1] - off;
    int half = lane >> 4, quad = lane & 15;

    float mx = dec_f(g_maxenc[n]);            // garbage if deg==0, unused then
    float4 acc = make_float4(0.f, 0.f, 0.f, 0.f);
    float sumex = 0.f;

    const float4* msg4 = (const float4*)g_msg;
    for (int t = half; t < deg; t += 2) {
        int e = g_csr[off + t];
        float ex = __expf(g_logit[e] - mx);
        int s = senders[e];
        float4 m = msg4[(size_t)s * 16 + quad];
        acc.x += ex * m.x; acc.y += ex * m.y;
        acc.z += ex * m.z; acc.w += ex * m.w;
        if (quad == 0) sumex += ex;
    }
    acc.x += __shfl_xor_sync(0xffffffffu, acc.x, 16);
    acc.y += __shfl_xor_sync(0xffffffffu, acc.y, 16);
    acc.z += __shfl_xor_sync(0xffffffffu, acc.z, 16);
    acc.w += __shfl_xor_sync(0xffffffffu, acc.w, 16);
    sumex += __shfl_xor_sync(0xffffffffu, sumex, 16);
    sumex = __shfl_sync(0xffffffffu, sumex, 0);

    if (lane < 16) {
        float inv = (deg > 0) ? (1.f / sumex) : 0.f;
        float4* o4 = (float4*)out_nodes;
        float4 o = o4[(size_t)n * 16 + lane];          // self-projection from K1
        o.x += acc.x * inv; o.y += acc.y * inv;
        o.z += acc.z * inv; o.w += acc.w * inv;
        o4[(size_t)n * 16 + lane] = o;
    }
}

// ---------------- launch ----------------
extern "C" void kernel_launch(void* const* d_in, const int* in_sizes, int n_in,
                              void* d_out, int out_size)
{
    const float* nodes     = (const float*)d_in[0];
    const float* edges     = (const float*)d_in[1];
    const int*   senders   = (const int*)  d_in[2];
    const int*   receivers = (const int*)  d_in[3];
    const float* W_sent = (const float*)d_in[4];  const float* b_sent = (const float*)d_in[5];
    const float* W_recv = (const float*)d_in[6];  const float* b_recv = (const float*)d_in[7];
    const float* W_edge = (const float*)d_in[8];  const float* b_edge = (const float*)d_in[9];
    const float* W_attn = (const float*)d_in[10]; const float* b_attn = (const float*)d_in[11];
    const float* W_msg  = (const float*)d_in[12]; const float* b_msg  = (const float*)d_in[13];
    const float* W_self = (const float*)d_in[14]; const float* b_self = (const float*)d_in[15];

    float* out_nodes = (float*)d_out;
    float* edge_feat = out_nodes + (size_t)N_NODES * D;

    const int smem_node = (128 * 65 + 64 * 64 + 64) * (int)sizeof(float);
    const int smem_edge = (128 * 65 + 64 * 64 + 128) * (int)sizeof(float);
    cudaFuncSetAttribute(k_node, cudaFuncAttributeMaxDynamicSharedMemorySize, smem_node);
    cudaFuncSetAttribute(k_edge, cudaFuncAttributeMaxDynamicSharedMemorySize, smem_edge);

    k_init<<<(N_NODES + 255) / 256, 256>>>();
    k_node<<<(N_NODES + 127) / 128, 256, smem_node>>>(
        nodes, W_sent, b_sent, W_recv, b_recv, W_msg, b_msg, W_self, b_self, out_nodes);
    k_edge<<<N_EDGES / 128, 256, smem_edge>>>(
        edges, senders, receivers, W_edge, b_edge, W_attn, b_attn, edge_feat);
    k_scan<<<1, 1024>>>();
    k_fill<<<N_EDGES / 256, 256>>>(receivers);
    k_aggregate<<<(N_NODES * 32 + 255) / 256, 256>>>(senders, out_nodes);
}

// round 2
// speedup vs baseline: 1.1704x; 1.1704x over previous
#include <cuda_runtime.h>
#include <math.h>

#define N_NODES 50000
#define N_EDGES 800000
#define D 64
#define SBLK 250
#define SNPB 200   // SBLK * SNPB == N_NODES

// ---------------- scratch (device globals: no allocation allowed) ----------------
__device__ float        g_sent[N_NODES * D];
__device__ float        g_recv[N_NODES * D];
__device__ float        g_msg [N_NODES * D];
__device__ float        g_logit[N_EDGES];
__device__ int          g_count[N_NODES];
__device__ int          g_part[SBLK];
__device__ int          g_rowoff[N_NODES + 1];
__device__ int          g_cursor[N_NODES];
__device__ int          g_csr[N_EDGES];

// ---------------- packed f32x2 helpers ----------------
__device__ __forceinline__ void ffma2(unsigned long long& d,
                                      unsigned long long a, unsigned long long b) {
    asm("fma.rn.f32x2 %0, %1, %2, %0;" : "+l"(d) : "l"(a), "l"(b));
}
__device__ __forceinline__ unsigned long long dup2(float a) {
    unsigned long long r;
    asm("mov.b64 %0, {%1, %1};" : "=l"(r) : "f"(a));
    return r;
}
__device__ __forceinline__ float2 unpack2(unsigned long long v) {
    float2 r;
    asm("mov.b64 {%0, %1}, %2;" : "=f"(r.x), "=f"(r.y) : "l"(v));
    return r;
}

// ---------------- K0: init counts ----------------
__global__ void k_init() {
    int i = blockIdx.x * blockDim.x + threadIdx.x;
    if (i < N_NODES) g_count[i] = 0;
}

// ---------------- K1: node projections (sent/recv/msg -> scratch, self -> d_out) ----------------
__global__ void k_node(const float* __restrict__ nodes,
                       const float* __restrict__ Ws, const float* __restrict__ bs,
                       const float* __restrict__ Wr, const float* __restrict__ br,
                       const float* __restrict__ Wm, const float* __restrict__ bm,
                       const float* __restrict__ Wf, const float* __restrict__ bf,
                       float* __restrict__ out_self)
{
    extern __shared__ float sm[];
    float (*sA)[65] = (float(*)[65])sm;       // 128 x 65
    float* sW = sm + 128 * 65;                // 64 x 64
    float* sb = sW + 64 * 64;                 // 64

    int tx = threadIdx.x;
    int n0 = blockIdx.x * 128;

    const float4* nd4 = (const float4*)nodes;
    for (int i = tx; i < 128 * 16; i += 256) {
        int row = i >> 4, c = (i & 15) * 4;
        float4 v = make_float4(0.f, 0.f, 0.f, 0.f);
        int gr = n0 + row;
        if (gr < N_NODES) v = nd4[(size_t)gr * 16 + (i & 15)];
        sA[row][c] = v.x; sA[row][c + 1] = v.y; sA[row][c + 2] = v.z; sA[row][c + 3] = v.w;
    }

    int cb = tx & 7, eb = tx >> 3;
    int c0 = cb * 8;

    const float* Wlist[4] = {Ws, Wr, Wm, Wf};
    const float* blist[4] = {bs, br, bm, bf};
    float*       olist[4] = {g_sent, g_recv, g_msg, out_self};

    #pragma unroll
    for (int m = 0; m < 4; m++) {
        __syncthreads();
        const float* W = Wlist[m];
        for (int i = tx; i < 4096; i += 256) sW[i] = W[i];
        if (tx < 64) sb[tx] = blist[m][tx];
        __syncthreads();

        unsigned long long acc[4][4];
        #pragma unroll
        for (int i = 0; i < 4; i++)
            #pragma unroll
            for (int j = 0; j < 4; j++) acc[i][j] = 0ull;

        #pragma unroll 4
        for (int k = 0; k < 64; k++) {
            ulonglong2 w0 = *(const ulonglong2*)&sW[k * 64 + c0];
            ulonglong2 w1 = *(const ulonglong2*)&sW[k * 64 + c0 + 4];
            #pragma unroll
            for (int i = 0; i < 4; i++) {
                unsigned long long a2 = dup2(sA[eb * 4 + i][k]);
                ffma2(acc[i][0], a2, w0.x);
                ffma2(acc[i][1], a2, w0.y);
                ffma2(acc[i][2], a2, w1.x);
                ffma2(acc[i][3], a2, w1.y);
            }
        }

        float bias[8];
        #pragma unroll
        for (int j = 0; j < 8; j++) bias[j] = sb[c0 + j];
        float* out = olist[m];
        #pragma unroll
        for (int i = 0; i < 4; i++) {
            int gr = n0 + eb * 4 + i;
            if (gr < N_NODES) {
                float2 p0 = unpack2(acc[i][0]), p1 = unpack2(acc[i][1]);
                float2 p2 = unpack2(acc[i][2]), p3 = unpack2(acc[i][3]);
                float4 o0 = make_float4(p0.x + bias[0], p0.y + bias[1],
                                        p1.x + bias[2], p1.y + bias[3]);
                float4 o1 = make_float4(p2.x + bias[4], p2.y + bias[5],
                                        p3.x + bias[6], p3.y + bias[7]);
                *(float4*)&out[(size_t)gr * 64 + c0]     = o0;
                *(float4*)&out[(size_t)gr * 64 + c0 + 4] = o1;
            }
        }
    }
}

// ---------------- K2: edge GEMM + fused epilogue ----------------
__global__ void k_edge(const float* __restrict__ edges,
                       const int* __restrict__ senders, const int* __restrict__ receivers,
                       const float* __restrict__ W_edge, const float* __restrict__ b_edge,
                       const float* __restrict__ W_attn, const float* __restrict__ b_attn,
                       float* __restrict__ edge_feat)
{
    extern __shared__ float sm[];
    float (*sA)[65] = (float(*)[65])sm;       // 128 x 65
    float* sW  = sm + 128 * 65;               // 64 x 64
    float* sb  = sW + 4096;                   // 64
    float* swa = sb + 64;                     // 64

    int tx = threadIdx.x;
    int e0 = blockIdx.x * 128;                // N_EDGES % 128 == 0

    const float4* eg4 = (const float4*)(edges + (size_t)e0 * 64);
    for (int i = tx; i < 128 * 16; i += 256) {
        float4 v = eg4[i];
        int row = i >> 4, c = (i & 15) * 4;
        sA[row][c] = v.x; sA[row][c + 1] = v.y; sA[row][c + 2] = v.z; sA[row][c + 3] = v.w;
    }
    for (int i = tx; i < 4096; i += 256) sW[i] = W_edge[i];
    if (tx < 64) { sb[tx] = b_edge[tx]; swa[tx] = W_attn[tx]; }
    __syncthreads();

    int cb = tx & 7, eb = tx >> 3;
    int c0 = cb * 8;

    unsigned long long acc[4][4];
    #pragma unroll
    for (int i = 0; i < 4; i++)
        #pragma unroll
        for (int j = 0; j < 4; j++) acc[i][j] = 0ull;

    #pragma unroll 4
    for (int k = 0; k < 64; k++) {
        ulonglong2 w0 = *(const ulonglong2*)&sW[k * 64 + c0];
        ulonglong2 w1 = *(const ulonglong2*)&sW[k * 64 + c0 + 4];
        #pragma unroll
        for (int i = 0; i < 4; i++) {
            unsigned long long a2 = dup2(sA[eb * 4 + i][k]);
            ffma2(acc[i][0], a2, w0.x);
            ffma2(acc[i][1], a2, w0.y);
            ffma2(acc[i][2], a2, w1.x);
            ffma2(acc[i][3], a2, w1.y);
        }
    }

    float bias[8], wa[8];
    #pragma unroll
    for (int j = 0; j < 8; j++) { bias[j] = sb[c0 + j]; wa[j] = swa[c0 + j]; }
    float battn = b_attn[0];

    #pragma unroll
    for (int i = 0; i < 4; i++) {
        int e = e0 + eb * 4 + i;
        int s = senders[e], r = receivers[e];
        const float4* ps = (const float4*)(g_sent + (size_t)s * 64 + c0);
        const float4* pr = (const float4*)(g_recv + (size_t)r * 64 + c0);
        float4 sv0 = ps[0], sv1 = ps[1];
        float4 rv0 = pr[0], rv1 = pr[1];
        float2 p0 = unpack2(acc[i][0]), p1 = unpack2(acc[i][1]);
        float2 p2 = unpack2(acc[i][2]), p3 = unpack2(acc[i][3]);

        float ef[8];
        ef[0] = p0.x + bias[0] + sv0.x + rv0.x;
        ef[1] = p0.y + bias[1] + sv0.y + rv0.y;
        ef[2] = p1.x + bias[2] + sv0.z + rv0.z;
        ef[3] = p1.y + bias[3] + sv0.w + rv0.w;
        ef[4] = p2.x + bias[4] + sv1.x + rv1.x;
        ef[5] = p2.y + bias[5] + sv1.y + rv1.y;
        ef[6] = p3.x + bias[6] + sv1.z + rv1.z;
        ef[7] = p3.y + bias[7] + sv1.w + rv1.w;

        *(float4*)&edge_feat[(size_t)e * 64 + c0]     = make_float4(ef[0], ef[1], ef[2], ef[3]);
        *(float4*)&edge_feat[(size_t)e * 64 + c0 + 4] = make_float4(ef[4], ef[5], ef[6], ef[7]);

        float p = ef[0]*wa[0] + ef[1]*wa[1] + ef[2]*wa[2] + ef[3]*wa[3]
                + ef[4]*wa[4] + ef[5]*wa[5] + ef[6]*wa[6] + ef[7]*wa[7];
        p += __shfl_xor_sync(0xffffffffu, p, 1);
        p += __shfl_xor_sync(0xffffffffu, p, 2);
        p += __shfl_xor_sync(0xffffffffu, p, 4);
        if (cb == 0) {
            float l = p + battn;
            l = (l > 0.f) ? l : 0.01f * l;     // leaky_relu, slope 0.01
            g_logit[e] = l;
            atomicAdd(&g_count[r], 1);
        }
    }
}

// ---------------- K3a: per-block partial sums of degree counts ----------------
__global__ void k_scan_a() {
    __shared__ int red[256];
    int b = blockIdx.x, t = threadIdx.x;
    int v = 0;
    if (t < SNPB) v = g_count[b * SNPB + t];
    red[t] = v;
    __syncthreads();
    for (int off = 128; off; off >>= 1) {
        if (t < off) red[t] += red[t + off];
        __syncthreads();
    }
    if (t == 0) g_part[b] = red[0];
}

// ---------------- K3b: per-block base + local exclusive scan ----------------
__global__ void k_scan_c() {
    __shared__ int sbase[256];
    __shared__ int sc[256];
    int b = blockIdx.x, t = threadIdx.x;

    int pv = (t < b) ? g_part[t] : 0;          // b < SBLK <= 256
    sbase[t] = pv;
    __syncthreads();
    for (int off = 128; off; off >>= 1) {
        if (t < off) sbase[t] += sbase[t + off];
        __syncthreads();
    }
    int base = sbase[0];

    int idx = b * SNPB + t;
    int c = (t < SNPB) ? g_count[idx] : 0;
    sc[t] = c;
    __syncthreads();
    for (int off = 1; off < 256; off <<= 1) {
        int v = 0;
        if (t >= off) v = sc[t - off];
        __syncthreads();
        if (t >= off) sc[t] += v;
        __syncthreads();
    }
    if (t < SNPB) {
        int ro = base + sc[t] - c;             // exclusive
        g_rowoff[idx] = ro;
        g_cursor[idx] = ro;
    }
    if (b == SBLK - 1 && t == SNPB - 1) g_rowoff[N_NODES] = base + sc[t];
}

// ---------------- K4: CSR fill ----------------
__global__ void k_fill(const int* __restrict__ receivers) {
    int e = blockIdx.x * blockDim.x + threadIdx.x;
    if (e < N_EDGES) {
        int r = receivers[e];
        int slot = atomicAdd(&g_cursor[r], 1);
        g_csr[slot] = e;
    }
}

// ---------------- K5: warp-per-node softmax-weighted aggregation ----------------
__global__ void k_aggregate(const int* __restrict__ senders,
                            float* __restrict__ out_nodes)
{
    int gid = blockIdx.x * blockDim.x + threadIdx.x;
    int n = gid >> 5;
    if (n >= N_NODES) return;
    int lane = gid & 31;
    int off = g_rowoff[n];
    int deg = g_rowoff[n + 1] - off;

    // pass 1: per-node max over logits (CSR + logits are L2-resident)
    float mx = -1e30f;
    for (int t = lane; t < deg; t += 32)
        mx = fmaxf(mx, g_logit[g_csr[off + t]]);
    #pragma unroll
    for (int o = 16; o; o >>= 1)
        mx = fmaxf(mx, __shfl_xor_sync(0xffffffffu, mx, o));

    // pass 2: accumulate exp-weighted messages
    int half = lane >> 4, quad = lane & 15;
    float4 acc = make_float4(0.f, 0.f, 0.f, 0.f);
    float sumex = 0.f;
    const float4* msg4 = (const float4*)g_msg;
    for (int t = half; t < deg; t += 2) {
        int e = g_csr[off + t];
        float ex = __expf(g_logit[e] - mx);
        int s = senders[e];
        float4 m = msg4[(size_t)s * 16 + quad];
        acc.x += ex * m.x; acc.y += ex * m.y;
        acc.z += ex * m.z; acc.w += ex * m.w;
        if (quad == 0) sumex += ex;
    }
    acc.x += __shfl_xor_sync(0xffffffffu, acc.x, 16);
    acc.y += __shfl_xor_sync(0xffffffffu, acc.y, 16);
    acc.z += __shfl_xor_sync(0xffffffffu, acc.z, 16);
    acc.w += __shfl_xor_sync(0xffffffffu, acc.w, 16);
    sumex += __shfl_xor_sync(0xffffffffu, sumex, 16);
    sumex = __shfl_sync(0xffffffffu, sumex, 0);

    if (lane < 16) {
        float inv = (deg > 0) ? (1.f / sumex) : 0.f;
        float4* o4 = (float4*)out_nodes;
        float4 o = o4[(size_t)n * 16 + lane];   // self-projection from K1
        o.x += acc.x * inv; o.y += acc.y * inv;
        o.z += acc.z * inv; o.w += acc.w * inv;
        o4[(size_t)n * 16 + lane] = o;
    }
}

// ---------------- launch ----------------
extern "C" void kernel_launch(void* const* d_in, const int* in_sizes, int n_in,
                              void* d_out, int out_size)
{
    const float* nodes     = (const float*)d_in[0];
    const float* edges     = (const float*)d_in[1];
    const int*   senders   = (const int*)  d_in[2];
    const int*   receivers = (const int*)  d_in[3];
    const float* W_sent = (const float*)d_in[4];  const float* b_sent = (const float*)d_in[5];
    const float* W_recv = (const float*)d_in[6];  const float* b_recv = (const float*)d_in[7];
    const float* W_edge = (const float*)d_in[8];  const float* b_edge = (const float*)d_in[9];
    const float* W_attn = (const float*)d_in[10]; const float* b_attn = (const float*)d_in[11];
    const float* W_msg  = (const float*)d_in[12]; const float* b_msg  = (const float*)d_in[13];
    const float* W_self = (const float*)d_in[14]; const float* b_self = (const float*)d_in[15];

    float* out_nodes = (float*)d_out;
    float* edge_feat = out_nodes + (size_t)N_NODES * D;

    const int smem_node = (128 * 65 + 64 * 64 + 64) * (int)sizeof(float);
    const int smem_edge = (128 * 65 + 64 * 64 + 128) * (int)sizeof(float);
    cudaFuncSetAttribute(k_node, cudaFuncAttributeMaxDynamicSharedMemorySize, smem_node);
    cudaFuncSetAttribute(k_edge, cudaFuncAttributeMaxDynamicSharedMemorySize, smem_edge);

    k_init<<<(N_NODES + 255) / 256, 256>>>();
    k_node<<<(N_NODES + 127) / 128, 256, smem_node>>>(
        nodes, W_sent, b_sent, W_recv, b_recv, W_msg, b_msg, W_self, b_self, out_nodes);
    k_edge<<<N_EDGES / 128, 256, smem_edge>>>(
        edges, senders, receivers, W_edge, b_edge, W_attn, b_attn, edge_feat);
    k_scan_a<<<SBLK, 256>>>();
    k_scan_c<<<SBLK, 256>>>();
    k_fill<<<N_EDGES / 256, 256>>>(receivers);
    k_aggregate<<<(N_NODES * 32 + 255) / 256, 256>>>(senders, out_nodes);
}